// round 2
// baseline (speedup 1.0000x reference)
#include <cuda_runtime.h>
#include <cstdint>

// ----------------------------------------------------------------------------
// Plain-sm_103 path (harness compiles PTX at target sm_103, no 'a' features):
// tf32 mma.sync (m16n8k8) + cp.async 3-stage pipeline.
//
//   h = relu(x @ W_init^T + b_init)        M=32768 N=2048 K=1024
//   o = relu(h @ W_ih^T  + b_ih + b_hh)    M=32768 N=2048 K=2048
//   y =       o @ W_final^T + b_final      M=32768 N=1024 K=2048
//
// CTA tile 128x256, BK=32, 8 warps (2M x 4N) with 64x64 warp tiles.
// k-permutation: present k-columns to the mma in order (0,4,1,5,2,6,3,7)^-1 on
// BOTH operands so each thread's fragment pair is memory-adjacent -> lds.64.
// ----------------------------------------------------------------------------

#define DINLINE __device__ __forceinline__

static constexpr int B_   = 16;
static constexpr int S_   = 2048;
static constexpr int DIN  = 1024;
static constexpr int DH   = 2048;
static constexpr int DACT = 1024;
static constexpr long MTOK = (long)B_ * S_;        // 32768

static constexpr int BM = 128;
static constexpr int BN = 256;
static constexpr int BK = 32;
static constexpr int STAGES = 3;
static constexpr int NTHR = 256;

static constexpr int LDW = BK + 8;                 // 40 words -> conflict-free
static constexpr int A_STAGE_B = BM * LDW * 4;     // 20480
static constexpr int B_STAGE_B = BN * LDW * 4;     // 40960
static constexpr int STAGE_B   = A_STAGE_B + B_STAGE_B;  // 61440
static constexpr int SMEM_TOTAL = STAGES * STAGE_B;      // 184320

DINLINE uint32_t smem_u32(const void* p) {
    uint32_t a;
    asm("{ .reg .u64 t; cvta.to.shared.u64 t, %1; cvt.u32.u64 %0, t; }"
        : "=r"(a) : "l"(p));
    return a;
}

#define CP_ASYNC16(dst, src) \
    asm volatile("cp.async.cg.shared.global [%0], [%1], 16;" \
        :: "r"((uint32_t)(dst)), "l"(src) : "memory")
#define CP_COMMIT() asm volatile("cp.async.commit_group;" ::: "memory")
#define CP_WAIT1()  asm volatile("cp.async.wait_group 1;" ::: "memory")

DINLINE void lds64(uint32_t& lo, uint32_t& hi, uint32_t addr) {
    asm volatile("ld.shared.v2.b32 {%0,%1}, [%2];" : "=r"(lo), "=r"(hi) : "r"(addr));
}

DINLINE void mma_tf32(float* c, const uint32_t* a, const uint32_t* b) {
    asm volatile(
        "mma.sync.aligned.m16n8k8.row.col.f32.tf32.tf32.f32 "
        "{%0,%1,%2,%3}, {%4,%5,%6,%7}, {%8,%9}, {%0,%1,%2,%3};"
        : "+f"(c[0]), "+f"(c[1]), "+f"(c[2]), "+f"(c[3])
        : "r"(a[0]), "r"(a[1]), "r"(a[2]), "r"(a[3]), "r"(b[0]), "r"(b[1]));
}

// ----------------------------------------------------------------------------
// Scratch (static device allocations -- allowed)
// ----------------------------------------------------------------------------
__device__ float g_x [MTOK * DIN];
__device__ float g_h [MTOK * DH];
__device__ float g_o [MTOK * DH];
__device__ float g_w1[(long)DH * DIN];
__device__ float g_w2[(long)DH * DH];
__device__ float g_w3[(long)DACT * DH];

// tf32 round-to-nearest pre-pass
__global__ void cvt_tf32_kernel(const float* __restrict__ in, float* __restrict__ out, int n4) {
    int i = blockIdx.x * blockDim.x + threadIdx.x;
    if (i < n4) {
        float4 v = reinterpret_cast<const float4*>(in)[i];
        uint32_t a, b, c, d;
        asm("cvt.rna.tf32.f32 %0, %1;" : "=r"(a) : "f"(v.x));
        asm("cvt.rna.tf32.f32 %0, %1;" : "=r"(b) : "f"(v.y));
        asm("cvt.rna.tf32.f32 %0, %1;" : "=r"(c) : "f"(v.z));
        asm("cvt.rna.tf32.f32 %0, %1;" : "=r"(d) : "f"(v.w));
        reinterpret_cast<uint4*>(out)[i] = make_uint4(a, b, c, d);
    }
}

// ----------------------------------------------------------------------------
// GEMM: C[M,N] = act(A[M,K] @ B[N,K]^T + bias1 (+ bias2))
// flags bit0 = relu, bit1 = round result to tf32
// ----------------------------------------------------------------------------
__global__ void __launch_bounds__(NTHR, 1)
gemm_tf32_kernel(const float* __restrict__ A, const float* __restrict__ Bw,
                 float* __restrict__ C,
                 const float* __restrict__ bias1, const float* __restrict__ bias2,
                 int M, int N, int K, int flags)
{
    extern __shared__ char smem[];
    const uint32_t sbase = smem_u32(smem);
    const int tid = threadIdx.x;
    const int wid = tid >> 5;
    const int lid = tid & 31;
    const int gid = lid >> 2;        // group 0..7
    const int tg  = lid & 3;         // thread-in-group 0..3

    const int ntiles = N / BN;
    const int nt = blockIdx.x % ntiles;
    const int mt = blockIdx.x / ntiles;
    const long m0 = (long)mt * BM;
    const int  n0 = nt * BN;

    const int warpM = wid >> 2;      // 0..1
    const int warpN = wid & 3;       // 0..3

    float acc[4][8][4];
    #pragma unroll
    for (int i = 0; i < 4; ++i)
        #pragma unroll
        for (int j = 0; j < 8; ++j)
            #pragma unroll
            for (int e = 0; e < 4; ++e) acc[i][j][e] = 0.0f;

    const int KT = K / BK;

    // ---- async tile loader (all 256 threads) --------------------------------
    auto load_stage = [&](int slot, int kt) {
        const uint32_t sA = sbase + slot * STAGE_B;
        const uint32_t sB = sA + A_STAGE_B;
        const int kb = kt * BK;
        #pragma unroll
        for (int i = 0; i < 4; ++i) {                 // A: 128 rows x 8 chunks
            const int ci = tid + NTHR * i;
            const int r = ci >> 3, c = ci & 7;
            CP_ASYNC16(sA + (r * LDW + c * 4) * 4,
                       A + (size_t)(m0 + r) * K + kb + c * 4);
        }
        #pragma unroll
        for (int i = 0; i < 8; ++i) {                 // B: 256 rows x 8 chunks
            const int ci = tid + NTHR * i;
            const int r = ci >> 3, c = ci & 7;
            CP_ASYNC16(sB + (r * LDW + c * 4) * 4,
                       Bw + (size_t)(n0 + r) * K + kb + c * 4);
        }
    };

    // prologue: fill STAGES-1 stages
    #pragma unroll
    for (int s = 0; s < STAGES - 1; ++s) { load_stage(s, s); CP_COMMIT(); }

    // per-thread fragment base offsets (words)
    const int aRowBase = warpM * 64 + gid;           // + mt*16 (+8)
    const int bRowBase = warpN * 64 + gid;           // + nt*8

    int slot = 0;
    for (int kt = 0; kt < KT; ++kt) {
        CP_WAIT1();
        __syncthreads();

        // refill the slot consumed two iterations ago
        if (kt + STAGES - 1 < KT) load_stage((kt + STAGES - 1) % STAGES, kt + STAGES - 1);
        CP_COMMIT();

        const uint32_t sA = sbase + slot * STAGE_B;
        const uint32_t sB = sA + A_STAGE_B;

        #pragma unroll
        for (int kk = 0; kk < 4; ++kk) {             // 4 x k8 steps
            const int kw = kk * 8 + 2 * tg;          // word offset in row
            uint32_t a[4][4], b[8][2];
            #pragma unroll
            for (int i = 0; i < 4; ++i) {
                const uint32_t ad = sA + ((aRowBase + i * 16) * LDW + kw) * 4;
                lds64(a[i][0], a[i][2], ad);                    // row r
                lds64(a[i][1], a[i][3], ad + 8 * LDW * 4);      // row r+8
            }
            #pragma unroll
            for (int j = 0; j < 8; ++j) {
                const uint32_t bd = sB + ((bRowBase + j * 8) * LDW + kw) * 4;
                lds64(b[j][0], b[j][1], bd);
            }
            #pragma unroll
            for (int i = 0; i < 4; ++i)
                #pragma unroll
                for (int j = 0; j < 8; ++j)
                    mma_tf32(acc[i][j], a[i], b[j]);
        }

        __syncthreads();
        slot = (slot + 1 == STAGES) ? 0 : slot + 1;
    }

    // ---- epilogue: bias + relu (+ tf32 round), store ------------------------
    const bool has2  = (bias2 != nullptr);
    const bool do_r  = (flags & 1);
    const bool do_rd = (flags & 2);
    const int ncol0 = n0 + warpN * 64;

    #pragma unroll
    for (int j = 0; j < 8; ++j) {
        const int col = ncol0 + j * 8 + 2 * tg;
        float bb0 = bias1[col],     bb1 = bias1[col + 1];
        if (has2) { bb0 += bias2[col]; bb1 += bias2[col + 1]; }
        #pragma unroll
        for (int i = 0; i < 4; ++i) {
            const long r0 = m0 + warpM * 64 + i * 16 + gid;
            #pragma unroll
            for (int h = 0; h < 2; ++h) {            // rows r0, r0+8
                float v0 = acc[i][j][2 * h + 0] + bb0;
                float v1 = acc[i][j][2 * h + 1] + bb1;
                if (do_r) { v0 = fmaxf(v0, 0.0f); v1 = fmaxf(v1, 0.0f); }
                if (do_rd) {
                    uint32_t u0, u1;
                    asm("cvt.rna.tf32.f32 %0, %1;" : "=r"(u0) : "f"(v0));
                    asm("cvt.rna.tf32.f32 %0, %1;" : "=r"(u1) : "f"(v1));
                    v0 = __uint_as_float(u0); v1 = __uint_as_float(u1);
                }
                float2 o = make_float2(v0, v1);
                *reinterpret_cast<float2*>(C + (size_t)(r0 + 8 * h) * N + col) = o;
            }
        }
    }
}

// ----------------------------------------------------------------------------
// Host launcher
// ----------------------------------------------------------------------------
extern "C" void kernel_launch(void* const* d_in, const int* in_sizes, int n_in,
                              void* d_out, int out_size)
{
    const float* x    = (const float*)d_in[0];
    const float* W1   = (const float*)d_in[1];
    const float* b1   = (const float*)d_in[2];
    const float* W2   = (const float*)d_in[3];
    const float* bih  = (const float*)d_in[4];
    const float* bhh  = (const float*)d_in[5];
    const float* W3   = (const float*)d_in[6];
    const float* b3   = (const float*)d_in[7];
    float* out = (float*)d_out;

    float *gx, *gh, *go, *gw1, *gw2, *gw3;
    cudaGetSymbolAddress((void**)&gx,  g_x);
    cudaGetSymbolAddress((void**)&gh,  g_h);
    cudaGetSymbolAddress((void**)&go,  g_o);
    cudaGetSymbolAddress((void**)&gw1, g_w1);
    cudaGetSymbolAddress((void**)&gw2, g_w2);
    cudaGetSymbolAddress((void**)&gw3, g_w3);

    cudaFuncSetAttribute(gemm_tf32_kernel,
                         cudaFuncAttributeMaxDynamicSharedMemorySize, SMEM_TOTAL);

    // tf32 round-to-nearest pre-pass
    {
        struct { const float* in; float* out; long n; } cv[4] = {
            { x,  gx,  MTOK * (long)DIN },
            { W1, gw1, (long)DH * DIN },
            { W2, gw2, (long)DH * DH },
            { W3, gw3, (long)DACT * DH },
        };
        for (int i = 0; i < 4; ++i) {
            int n4 = (int)(cv[i].n / 4);
            cvt_tf32_kernel<<<(n4 + 255) / 256, 256>>>(cv[i].in, cv[i].out, n4);
        }
    }

    const int Mtiles = (int)(MTOK / BM);   // 256

    // GEMM1: h = relu(x @ W1^T + b1), round to tf32
    gemm_tf32_kernel<<<Mtiles * (DH / BN), NTHR, SMEM_TOTAL>>>(
        gx, gw1, gh, b1, nullptr, (int)MTOK, DH, DIN, 3);

    // GEMM2: o = relu(h @ W2^T + bih + bhh), round to tf32
    gemm_tf32_kernel<<<Mtiles * (DH / BN), NTHR, SMEM_TOTAL>>>(
        gh, gw2, go, bih, bhh, (int)MTOK, DH, DH, 3);

    // GEMM3: y = o @ W3^T + b3 (fp32 out)
    gemm_tf32_kernel<<<Mtiles * (DACT / BN), NTHR, SMEM_TOTAL>>>(
        go, gw3, out, b3, nullptr, (int)MTOK, DACT, DH, 0);

    (void)in_sizes; (void)n_in; (void)out_size;
}

// round 3
// speedup vs baseline: 1.8271x; 1.8271x over previous
#include <cuda_runtime.h>
#include <cuda_fp16.h>
#include <cstdint>

// ----------------------------------------------------------------------------
// fp16 mma.sync m16n8k16 + ldmatrix + cp.async 3-stage pipeline (plain sm_103).
//
//   h = relu(x @ W_init^T + b_init)        M=32768 N=2048 K=1024
//   o = relu(h @ W_ih^T  + b_ih + b_hh)    M=32768 N=2048 K=2048
//   y =       o @ W_final^T + b_final      M=32768 N=1024 K=2048
//
// Inputs/weights/intermediates rounded to fp16 (same 10-bit mantissa as tf32,
// fp32 accumulation -> rel_err ~5e-4). CTA tile 128x256, BK=64, 8 warps with
// 64x64 warp tiles. A and B both K-contiguous -> plain (non-trans) ldmatrix.x4.
// ----------------------------------------------------------------------------

#define DINLINE __device__ __forceinline__

static constexpr int B_   = 16;
static constexpr int S_   = 2048;
static constexpr int DIN  = 1024;
static constexpr int DH   = 2048;
static constexpr int DACT = 1024;
static constexpr long MTOK = (long)B_ * S_;        // 32768

static constexpr int BM = 128;
static constexpr int BN = 256;
static constexpr int BK = 64;                      // halves; 128B per row
static constexpr int STAGES = 3;
static constexpr int NTHR = 256;

static constexpr int ROWB = BK * 2 + 16;           // 144B row stride, ldmatrix-conflict-free
static constexpr int A_STAGE_B = BM * ROWB;        // 18432
static constexpr int B_STAGE_B = BN * ROWB;        // 36864
static constexpr int STAGE_B   = A_STAGE_B + B_STAGE_B;   // 55296
static constexpr int SMEM_TOTAL = STAGES * STAGE_B;       // 165888

DINLINE uint32_t smem_u32(const void* p) {
    uint32_t a;
    asm("{ .reg .u64 t; cvta.to.shared.u64 t, %1; cvt.u32.u64 %0, t; }"
        : "=r"(a) : "l"(p));
    return a;
}

#define CP_ASYNC16(dst, src) \
    asm volatile("cp.async.cg.shared.global [%0], [%1], 16;" \
        :: "r"((uint32_t)(dst)), "l"(src) : "memory")
#define CP_COMMIT() asm volatile("cp.async.commit_group;" ::: "memory")
#define CP_WAIT1()  asm volatile("cp.async.wait_group 1;" ::: "memory")

DINLINE void ldsm_x4(uint32_t* r, uint32_t addr) {
    asm volatile("ldmatrix.sync.aligned.m8n8.x4.shared.b16 {%0,%1,%2,%3}, [%4];"
        : "=r"(r[0]), "=r"(r[1]), "=r"(r[2]), "=r"(r[3]) : "r"(addr));
}

DINLINE void mma_f16(float* c, const uint32_t* a, const uint32_t* b) {
    asm volatile(
        "mma.sync.aligned.m16n8k16.row.col.f32.f16.f16.f32 "
        "{%0,%1,%2,%3}, {%4,%5,%6,%7}, {%8,%9}, {%0,%1,%2,%3};"
        : "+f"(c[0]), "+f"(c[1]), "+f"(c[2]), "+f"(c[3])
        : "r"(a[0]), "r"(a[1]), "r"(a[2]), "r"(a[3]), "r"(b[0]), "r"(b[1]));
}

// ----------------------------------------------------------------------------
// Scratch (static device allocations -- allowed)
// ----------------------------------------------------------------------------
__device__ __half g_x [MTOK * DIN];
__device__ __half g_h [MTOK * DH];
__device__ __half g_o [MTOK * DH];
__device__ __half g_w1[(long)DH * DIN];
__device__ __half g_w2[(long)DH * DH];
__device__ __half g_w3[(long)DACT * DH];

// fp32 -> fp16 round-to-nearest pre-pass
__global__ void cvt_f16_kernel(const float* __restrict__ in, __half* __restrict__ out, int n4) {
    int i = blockIdx.x * blockDim.x + threadIdx.x;
    if (i < n4) {
        float4 v = reinterpret_cast<const float4*>(in)[i];
        __half2 p0 = __floats2half2_rn(v.x, v.y);
        __half2 p1 = __floats2half2_rn(v.z, v.w);
        uint2 o = make_uint2(*reinterpret_cast<uint32_t*>(&p0),
                             *reinterpret_cast<uint32_t*>(&p1));
        reinterpret_cast<uint2*>(out)[i] = o;
    }
}

// ----------------------------------------------------------------------------
// GEMM: C[M,N] = act(A[M,K] @ B[N,K]^T + bias1 (+ bias2))
// HALF_OUT: store fp16 (round-to-nearest); RELU: apply relu.
// ----------------------------------------------------------------------------
template <bool HALF_OUT, bool RELU>
__global__ void __launch_bounds__(NTHR, 1)
gemm_f16_kernel(const __half* __restrict__ A, const __half* __restrict__ Bw,
                void* __restrict__ Cv,
                const float* __restrict__ bias1, const float* __restrict__ bias2,
                int M, int N, int K)
{
    extern __shared__ char smem[];
    const uint32_t sbase = smem_u32(smem);
    const int tid = threadIdx.x;
    const int wid = tid >> 5;
    const int lid = tid & 31;
    const int g   = lid >> 2;        // group 0..7
    const int tg  = lid & 3;         // thread-in-group

    const int ntiles = N / BN;
    const int nt = blockIdx.x % ntiles;
    const int mt = blockIdx.x / ntiles;
    const long m0 = (long)mt * BM;
    const int  n0 = nt * BN;

    const int warpM = wid >> 2;      // 0..1
    const int warpN = wid & 3;       // 0..3

    float acc[4][8][4];
    #pragma unroll
    for (int i = 0; i < 4; ++i)
        #pragma unroll
        for (int j = 0; j < 8; ++j)
            #pragma unroll
            for (int e = 0; e < 4; ++e) acc[i][j][e] = 0.0f;

    const int KT = K / BK;

    // ---- async tile loader (all 256 threads; 16B chunks = 8 halves) --------
    auto load_stage = [&](int slot, int kt) {
        const uint32_t sA = sbase + slot * STAGE_B;
        const uint32_t sB = sA + A_STAGE_B;
        const int kb = kt * BK;
        #pragma unroll
        for (int i = 0; i < 4; ++i) {                 // A: 128 rows x 8 chunks
            const int ci = tid + NTHR * i;
            const int r = ci >> 3, c = ci & 7;
            CP_ASYNC16(sA + r * ROWB + c * 16,
                       A + (size_t)(m0 + r) * K + kb + c * 8);
        }
        #pragma unroll
        for (int i = 0; i < 8; ++i) {                 // B: 256 rows x 8 chunks
            const int ci = tid + NTHR * i;
            const int r = ci >> 3, c = ci & 7;
            CP_ASYNC16(sB + r * ROWB + c * 16,
                       Bw + (size_t)(n0 + r) * K + kb + c * 8);
        }
    };

    #pragma unroll
    for (int s = 0; s < STAGES - 1; ++s) { load_stage(s, s); CP_COMMIT(); }

    // ---- per-lane ldmatrix address offsets (relative to stage base) --------
    const int lm = lid >> 3;                         // matrix index 0..3
    // A x4: m0 rows0-7/kLo, m1 rows8-15/kLo, m2 rows0-7/kHi, m3 rows8-15/kHi
    const int aRow  = warpM * 64 + ((lm & 1) << 3) + (lid & 7);
    const int aColB = (lm >> 1) << 4;
    // B x4: m0 n0-7/kLo, m1 n0-7/kHi, m2 n8-15/kLo, m3 n8-15/kHi
    const int bRow  = warpN * 64 + ((lm >> 1) << 3) + (lid & 7);
    const int bColB = (lm & 1) << 4;
    uint32_t aOff[4], bOff[4];
    #pragma unroll
    for (int i = 0; i < 4; ++i) aOff[i] = (aRow + i * 16) * ROWB + aColB;
    #pragma unroll
    for (int jp = 0; jp < 4; ++jp) bOff[jp] = (bRow + jp * 16) * ROWB + bColB;

    int slot = 0;
    for (int kt = 0; kt < KT; ++kt) {
        CP_WAIT1();
        __syncthreads();

        if (kt + STAGES - 1 < KT) load_stage((kt + STAGES - 1) % STAGES, kt + STAGES - 1);
        CP_COMMIT();

        const uint32_t sA = sbase + slot * STAGE_B;
        const uint32_t sB = sA + A_STAGE_B;

        #pragma unroll
        for (int kk = 0; kk < 4; ++kk) {             // 4 x k16 steps
            uint32_t a[4][4], b[4][4];
            #pragma unroll
            for (int i = 0; i < 4; ++i)  ldsm_x4(a[i],  sA + aOff[i]  + kk * 32);
            #pragma unroll
            for (int jp = 0; jp < 4; ++jp) ldsm_x4(b[jp], sB + bOff[jp] + kk * 32);
            #pragma unroll
            for (int i = 0; i < 4; ++i)
                #pragma unroll
                for (int j = 0; j < 8; ++j)
                    mma_f16(acc[i][j], a[i], &b[j >> 1][(j & 1) * 2]);
        }

        slot = (slot + 1 == STAGES) ? 0 : slot + 1;
    }

    // ---- epilogue ----------------------------------------------------------
    const bool has2 = (bias2 != nullptr);
    const int jb0 = n0 + warpN * 64;

    #pragma unroll
    for (int j = 0; j < 8; ++j) {
        const int col = jb0 + j * 8 + 2 * tg;
        float bb0 = bias1[col], bb1 = bias1[col + 1];
        if (has2) { bb0 += bias2[col]; bb1 += bias2[col + 1]; }
        #pragma unroll
        for (int i = 0; i < 4; ++i) {
            const long r0 = m0 + warpM * 64 + i * 16 + g;
            #pragma unroll
            for (int h = 0; h < 2; ++h) {            // rows r0, r0+8
                float v0 = acc[i][j][2 * h + 0] + bb0;
                float v1 = acc[i][j][2 * h + 1] + bb1;
                if (RELU) { v0 = fmaxf(v0, 0.0f); v1 = fmaxf(v1, 0.0f); }
                const size_t idx = (size_t)(r0 + 8 * h) * N + col;
                if (HALF_OUT) {
                    __half2 hv = __floats2half2_rn(v0, v1);
                    *reinterpret_cast<uint32_t*>((__half*)Cv + idx) =
                        *reinterpret_cast<uint32_t*>(&hv);
                } else {
                    *reinterpret_cast<float2*>((float*)Cv + idx) = make_float2(v0, v1);
                }
            }
        }
    }
}

// ----------------------------------------------------------------------------
// Host launcher
// ----------------------------------------------------------------------------
extern "C" void kernel_launch(void* const* d_in, const int* in_sizes, int n_in,
                              void* d_out, int out_size)
{
    const float* x    = (const float*)d_in[0];
    const float* W1   = (const float*)d_in[1];
    const float* b1   = (const float*)d_in[2];
    const float* W2   = (const float*)d_in[3];
    const float* bih  = (const float*)d_in[4];
    const float* bhh  = (const float*)d_in[5];
    const float* W3   = (const float*)d_in[6];
    const float* b3   = (const float*)d_in[7];
    float* out = (float*)d_out;

    __half *gx, *gh, *go, *gw1, *gw2, *gw3;
    cudaGetSymbolAddress((void**)&gx,  g_x);
    cudaGetSymbolAddress((void**)&gh,  g_h);
    cudaGetSymbolAddress((void**)&go,  g_o);
    cudaGetSymbolAddress((void**)&gw1, g_w1);
    cudaGetSymbolAddress((void**)&gw2, g_w2);
    cudaGetSymbolAddress((void**)&gw3, g_w3);

    cudaFuncSetAttribute(gemm_f16_kernel<true, true>,
                         cudaFuncAttributeMaxDynamicSharedMemorySize, SMEM_TOTAL);
    cudaFuncSetAttribute(gemm_f16_kernel<false, false>,
                         cudaFuncAttributeMaxDynamicSharedMemorySize, SMEM_TOTAL);

    // fp32 -> fp16 pre-pass
    {
        struct { const float* in; __half* out; long n; } cv[4] = {
            { x,  gx,  MTOK * (long)DIN },
            { W1, gw1, (long)DH * DIN },
            { W2, gw2, (long)DH * DH },
            { W3, gw3, (long)DACT * DH },
        };
        for (int i = 0; i < 4; ++i) {
            int n4 = (int)(cv[i].n / 4);
            cvt_f16_kernel<<<(n4 + 255) / 256, 256>>>(cv[i].in, cv[i].out, n4);
        }
    }

    const int Mtiles = (int)(MTOK / BM);   // 256

    // GEMM1: h = relu(x @ W1^T + b1) -> fp16
    gemm_f16_kernel<true, true><<<Mtiles * (DH / BN), NTHR, SMEM_TOTAL>>>(
        gx, gw1, gh, b1, nullptr, (int)MTOK, DH, DIN);

    // GEMM2: o = relu(h @ W2^T + bih + bhh) -> fp16
    gemm_f16_kernel<true, true><<<Mtiles * (DH / BN), NTHR, SMEM_TOTAL>>>(
        gh, gw2, go, bih, bhh, (int)MTOK, DH, DH);

    // GEMM3: y = o @ W3^T + b3 -> fp32
    gemm_f16_kernel<false, false><<<Mtiles * (DACT / BN), NTHR, SMEM_TOTAL>>>(
        go, gw3, out, b3, nullptr, (int)MTOK, DACT, DH);

    (void)in_sizes; (void)n_in; (void)out_size;
}

// round 4
// speedup vs baseline: 2.5812x; 1.4128x over previous
#include <cuda_runtime.h>
#include <cuda_fp16.h>
#include <cstdint>

// ----------------------------------------------------------------------------
// fp16 mma.sync m16n8k16 + ldmatrix, cp.async.bulk (1D) + mbarrier pipeline.
// Data pre-tiled into SW128-swizzled contiguous panels so each K-stage is a
// single 16KB (A) + 32KB (B) bulk copy issued by one thread.
//
//   h = relu(x @ W_init^T + b_init)        M=32768 N=2048 K=1024
//   o = relu(h @ W_ih^T  + b_ih + b_hh)    M=32768 N=2048 K=2048
//   y =       o @ W_final^T + b_final      M=32768 N=1024 K=2048
//
// CTA tile 128x256, BK=64, 4-stage mbarrier pipeline, 8 warps (2Mx4N, 64x64).
// ----------------------------------------------------------------------------

#define DINLINE __device__ __forceinline__

static constexpr int DIN  = 1024;
static constexpr int DH   = 2048;
static constexpr int DACT = 1024;
static constexpr long MTOK = 32768;

static constexpr int BM = 128;
static constexpr int BN = 256;
static constexpr int BK = 64;            // 128B rows
static constexpr int STAGES = 4;
static constexpr int NTHR = 256;

static constexpr int A_ST = BM * BK * 2;         // 16384 B
static constexpr int B_ST = BN * BK * 2;         // 32768 B
static constexpr int STG  = A_ST + B_ST;         // 49152 B
static constexpr int HDR  = 1024;
static constexpr int SMEM_TOTAL = HDR + STAGES * STG;   // 197632

DINLINE uint32_t smem_u32(const void* p) {
    uint32_t a;
    asm("{ .reg .u64 t; cvta.to.shared.u64 t, %1; cvt.u32.u64 %0, t; }"
        : "=r"(a) : "l"(p));
    return a;
}

#define MBARRIER_INIT(addr, cnt) \
    asm volatile("mbarrier.init.shared.b64 [%0], %1;" :: "r"(addr), "r"(cnt) : "memory")
#define MBARRIER_ARRIVE(addr) \
    asm volatile("mbarrier.arrive.shared.b64 _, [%0];" :: "r"(addr) : "memory")
#define MBARRIER_EXPECT_TX(addr, n) \
    asm volatile("mbarrier.arrive.expect_tx.shared.b64 _, [%0], %1;" :: "r"(addr), "r"(n) : "memory")

#define MBARRIER_WAIT_PARITY(mbar_smem_addr, phase_parity) do { \
    uint32_t _mbar = (uint32_t)(mbar_smem_addr); \
    uint32_t _parity = (uint32_t)(phase_parity); \
    uint32_t _done; \
    asm volatile( \
        "{\n\t" \
        ".reg .pred p;\n\t" \
        "mbarrier.try_wait.parity.shared.b64 p, [%1], %2;\n\t" \
        "selp.b32 %0, 1, 0, p;\n\t" \
        "}" \
        : "=r"(_done) : "r"(_mbar), "r"(_parity) : "memory"); \
    if (!_done) { \
        asm volatile( \
            "{\n\t" \
            ".reg .pred P1;\n\t" \
            "WAIT_LOOP_%=:\n\t" \
            "mbarrier.try_wait.parity.shared.b64 P1, [%0], %1, 0x989680;\n\t" \
            "@P1 bra.uni WAIT_DONE_%=;\n\t" \
            "bra.uni WAIT_LOOP_%=;\n\t" \
            "WAIT_DONE_%=:\n\t" \
            "}" \
            :: "r"(_mbar), "r"(_parity) : "memory"); \
    } \
} while(0)

#define BULK_G2S(dst, src, sz, mbar) \
    asm volatile("cp.async.bulk.shared::cta.global.mbarrier::complete_tx::bytes [%0], [%1], %2, [%3];" \
        :: "r"((uint32_t)(dst)), "l"(src), "r"((uint32_t)(sz)), "r"((uint32_t)(mbar)) : "memory")

DINLINE void ldsm_x4(uint32_t* r, uint32_t addr) {
    asm volatile("ldmatrix.sync.aligned.m8n8.x4.shared.b16 {%0,%1,%2,%3}, [%4];"
        : "=r"(r[0]), "=r"(r[1]), "=r"(r[2]), "=r"(r[3]) : "r"(addr));
}

DINLINE void mma_f16(float* c, const uint32_t* a, const uint32_t* b) {
    asm volatile(
        "mma.sync.aligned.m16n8k16.row.col.f32.f16.f16.f32 "
        "{%0,%1,%2,%3}, {%4,%5,%6,%7}, {%8,%9}, {%0,%1,%2,%3};"
        : "+f"(c[0]), "+f"(c[1]), "+f"(c[2]), "+f"(c[3])
        : "r"(a[0]), "r"(a[1]), "r"(a[2]), "r"(a[3]), "r"(b[0]), "r"(b[1]));
}

// ----------------------------------------------------------------------------
// Scratch (static device allocations -- allowed). All in swizzled panel layout.
// ----------------------------------------------------------------------------
__device__ __half g_x [MTOK * DIN];
__device__ __half g_h [MTOK * DH];
__device__ __half g_o [MTOK * DH];
__device__ __half g_w1[(long)DH * DIN];
__device__ __half g_w2[(long)DH * DH];
__device__ __half g_w3[(long)DACT * DH];

// ----------------------------------------------------------------------------
// fp32 -> fp16 + tile/swizzle pre-pass.
// Panel layout (RP = 128 for A-operands, 256 for B-operands):
//   panel (r/RP, c/64), within: row (r%RP) of 8 granules (16B each),
//   granule index swizzled: g' = g ^ (r&7).
// One thread handles one 16B output granule (8 halves).
// ----------------------------------------------------------------------------
template <int RP>
__global__ void cvt_tile_kernel(const float* __restrict__ in, __half* __restrict__ out,
                                int kshift /* log2(K/8) */, int ng) {
    int gi = blockIdx.x * blockDim.x + threadIdx.x;
    if (gi >= ng) return;
    const int gperrow = 1 << kshift;
    const int c8 = gi & (gperrow - 1);
    const int r  = gi >> kshift;
    const float4* f4 = reinterpret_cast<const float4*>(in);
    float4 v0 = f4[2 * (size_t)gi], v1 = f4[2 * (size_t)gi + 1];
    __half2 h0 = __floats2half2_rn(v0.x, v0.y), h1 = __floats2half2_rn(v0.z, v0.w);
    __half2 h2 = __floats2half2_rn(v1.x, v1.y), h3 = __floats2half2_rn(v1.z, v1.w);
    uint4 o = make_uint4(*reinterpret_cast<uint32_t*>(&h0), *reinterpret_cast<uint32_t*>(&h1),
                         *reinterpret_cast<uint32_t*>(&h2), *reinterpret_cast<uint32_t*>(&h3));
    const size_t panel = (size_t)(r / RP) * (gperrow >> 3) + (c8 >> 3);
    const size_t gip   = (size_t)(r % RP) * 8 + ((c8 & 7) ^ (r & 7));
    reinterpret_cast<uint4*>(out)[panel * (RP * 8) + gip] = o;
}

// ----------------------------------------------------------------------------
// GEMM: C = act(A @ B^T + bias1 (+bias2)); A,B in swizzled panels.
// HALF_OUT -> write C as swizzled 128-row panels (next GEMM's A); else fp32 row-major.
// ----------------------------------------------------------------------------
template <bool HALF_OUT, bool RELU>
__global__ void __launch_bounds__(NTHR, 1)
gemm_f16_kernel(const __half* __restrict__ A, const __half* __restrict__ Bw,
                void* __restrict__ Cv,
                const float* __restrict__ bias1, const float* __restrict__ bias2,
                int N, int KT)
{
    extern __shared__ char smem[];
    const uint32_t sbase = smem_u32(smem);
    const int tid = threadIdx.x;
    const int wid = tid >> 5;
    const int lid = tid & 31;
    const int g   = lid >> 2;
    const int tg  = lid & 3;

    const int ntiles = N / BN;
    const int nt = blockIdx.x % ntiles;
    const int mt = blockIdx.x / ntiles;
    const long m0 = (long)mt * BM;
    const int  n0 = nt * BN;

    const int warpM = wid >> 2;
    const int warpN = wid & 3;

    // mbarriers: full[s] @ 8s, empty[s] @ 64+8s
    if (tid == 0) {
        #pragma unroll
        for (int s = 0; s < STAGES; ++s) {
            MBARRIER_INIT(sbase + 8 * s, 1);
            MBARRIER_INIT(sbase + 64 + 8 * s, 8);
        }
    }
    __syncthreads();

    const __half* aPan = A  + (size_t)mt * KT * (A_ST / 2);
    const __half* bPan = Bw + (size_t)nt * KT * (B_ST / 2);

    // prologue: fill stages 0..STAGES-2
    if (tid == 0) {
        #pragma unroll
        for (int s = 0; s < STAGES - 1; ++s) {
            const uint32_t st = sbase + HDR + s * STG;
            MBARRIER_EXPECT_TX(sbase + 8 * s, STG);
            BULK_G2S(st,        aPan + (size_t)s * (A_ST / 2), A_ST, sbase + 8 * s);
            BULK_G2S(st + A_ST, bPan + (size_t)s * (B_ST / 2), B_ST, sbase + 8 * s);
        }
    }

    float acc[4][8][4];
    #pragma unroll
    for (int i = 0; i < 4; ++i)
        #pragma unroll
        for (int j = 0; j < 8; ++j)
            #pragma unroll
            for (int e = 0; e < 4; ++e) acc[i][j][e] = 0.0f;

    // ldmatrix per-lane bases (swizzled granule addressing)
    const int lm   = lid >> 3;
    const int aRow = warpM * 64 + ((lm & 1) << 3) + (lid & 7);
    const int asel = lm >> 1;
    const int aXor = aRow & 7;
    const int bRow = warpN * 64 + ((lm >> 1) << 3) + (lid & 7);
    const int bsel = lm & 1;
    const int bXor = bRow & 7;
    uint32_t aBase[4], bBase[4];
    #pragma unroll
    for (int i = 0; i < 4; ++i) aBase[i] = (uint32_t)(aRow + i * 16) * 128;
    #pragma unroll
    for (int jp = 0; jp < 4; ++jp) bBase[jp] = (uint32_t)(bRow + jp * 16) * 128;

    for (int kt = 0; kt < KT; ++kt) {
        const int s = kt & (STAGES - 1);

        // producer: refill stage kt+STAGES-1
        const int f = kt + STAGES - 1;
        if (tid == 0 && f < KT) {
            const int s2 = f & (STAGES - 1);
            if (f >= STAGES)
                MBARRIER_WAIT_PARITY(sbase + 64 + 8 * s2, ((f >> 2) - 1) & 1);
            const uint32_t st = sbase + HDR + s2 * STG;
            MBARRIER_EXPECT_TX(sbase + 8 * s2, STG);
            BULK_G2S(st,        aPan + (size_t)f * (A_ST / 2), A_ST, sbase + 8 * s2);
            BULK_G2S(st + A_ST, bPan + (size_t)f * (B_ST / 2), B_ST, sbase + 8 * s2);
        }

        MBARRIER_WAIT_PARITY(sbase + 8 * s, (kt >> 2) & 1);

        const uint32_t sA = sbase + HDR + s * STG;
        const uint32_t sB = sA + A_ST;

        #pragma unroll
        for (int kk = 0; kk < 4; ++kk) {
            uint32_t a[4][4], b[4][4];
            const uint32_t aoff = (uint32_t)(((kk * 2 + asel) ^ aXor) << 4);
            const uint32_t boff = (uint32_t)(((kk * 2 + bsel) ^ bXor) << 4);
            #pragma unroll
            for (int i = 0; i < 4; ++i)   ldsm_x4(a[i],  sA + aBase[i]  + aoff);
            #pragma unroll
            for (int jp = 0; jp < 4; ++jp) ldsm_x4(b[jp], sB + bBase[jp] + boff);
            #pragma unroll
            for (int i = 0; i < 4; ++i)
                #pragma unroll
                for (int j = 0; j < 8; ++j)
                    mma_f16(acc[i][j], a[i], &b[j >> 1][(j & 1) * 2]);
        }

        __syncwarp();
        if (lid == 0) MBARRIER_ARRIVE(sbase + 64 + 8 * s);
    }

    // ---- epilogue ----------------------------------------------------------
    const bool has2 = (bias2 != nullptr);
    const int jb0 = n0 + warpN * 64;

    #pragma unroll
    for (int j = 0; j < 8; ++j) {
        const int col = jb0 + j * 8 + 2 * tg;
        float bb0 = bias1[col], bb1 = bias1[col + 1];
        if (has2) { bb0 += bias2[col]; bb1 += bias2[col + 1]; }
        #pragma unroll
        for (int i = 0; i < 4; ++i) {
            const long r0 = m0 + warpM * 64 + i * 16 + g;
            #pragma unroll
            for (int h = 0; h < 2; ++h) {
                const long r = r0 + 8 * h;
                float v0 = acc[i][j][2 * h + 0] + bb0;
                float v1 = acc[i][j][2 * h + 1] + bb1;
                if (RELU) { v0 = fmaxf(v0, 0.0f); v1 = fmaxf(v1, 0.0f); }
                if (HALF_OUT) {
                    // swizzled 128-row panel layout (next GEMM's A operand)
                    __half2 hv = __floats2half2_rn(v0, v1);
                    const size_t panel = ((size_t)(r >> 7) * (N >> 6) + (col >> 6)) << 13;
                    const size_t off = panel + (size_t)((int)(r & 127)) * 64
                                     + (size_t)(((((col >> 3) & 7) ^ ((int)r & 7)) << 3) + (col & 7));
                    *reinterpret_cast<uint32_t*>((__half*)Cv + off) =
                        *reinterpret_cast<uint32_t*>(&hv);
                } else {
                    *reinterpret_cast<float2*>((float*)Cv + (size_t)r * N + col) =
                        make_float2(v0, v1);
                }
            }
        }
    }
}

// ----------------------------------------------------------------------------
// Host launcher
// ----------------------------------------------------------------------------
extern "C" void kernel_launch(void* const* d_in, const int* in_sizes, int n_in,
                              void* d_out, int out_size)
{
    const float* x    = (const float*)d_in[0];
    const float* W1   = (const float*)d_in[1];
    const float* b1   = (const float*)d_in[2];
    const float* W2   = (const float*)d_in[3];
    const float* bih  = (const float*)d_in[4];
    const float* bhh  = (const float*)d_in[5];
    const float* W3   = (const float*)d_in[6];
    const float* b3   = (const float*)d_in[7];
    float* out = (float*)d_out;

    __half *gx, *gh, *go, *gw1, *gw2, *gw3;
    cudaGetSymbolAddress((void**)&gx,  g_x);
    cudaGetSymbolAddress((void**)&gh,  g_h);
    cudaGetSymbolAddress((void**)&go,  g_o);
    cudaGetSymbolAddress((void**)&gw1, g_w1);
    cudaGetSymbolAddress((void**)&gw2, g_w2);
    cudaGetSymbolAddress((void**)&gw3, g_w3);

    cudaFuncSetAttribute(gemm_f16_kernel<true, true>,
                         cudaFuncAttributeMaxDynamicSharedMemorySize, SMEM_TOTAL);
    cudaFuncSetAttribute(gemm_f16_kernel<false, false>,
                         cudaFuncAttributeMaxDynamicSharedMemorySize, SMEM_TOTAL);

    // pre-pass: fp32 -> fp16 into swizzled panels
    {
        int ng;
        ng = (int)(MTOK * (long)DIN / 8);              // x: RP=128, K=1024
        cvt_tile_kernel<128><<<(ng + 255) / 256, 256>>>(x, gx, 7, ng);
        ng = (int)((long)DH * DIN / 8);                // W1: RP=256, K=1024
        cvt_tile_kernel<256><<<(ng + 255) / 256, 256>>>(W1, gw1, 7, ng);
        ng = (int)((long)DH * DH / 8);                 // W2: RP=256, K=2048
        cvt_tile_kernel<256><<<(ng + 255) / 256, 256>>>(W2, gw2, 8, ng);
        ng = (int)((long)DACT * DH / 8);               // W3: RP=256, K=2048
        cvt_tile_kernel<256><<<(ng + 255) / 256, 256>>>(W3, gw3, 8, ng);
    }

    const int Mtiles = (int)(MTOK / BM);   // 256

    // GEMM1: h = relu(x @ W1^T + b1) -> fp16 panels      (KT=16)
    gemm_f16_kernel<true, true><<<Mtiles * (DH / BN), NTHR, SMEM_TOTAL>>>(
        gx, gw1, gh, b1, nullptr, DH, DIN / BK);

    // GEMM2: o = relu(h @ W2^T + bih + bhh) -> fp16 panels (KT=32)
    gemm_f16_kernel<true, true><<<Mtiles * (DH / BN), NTHR, SMEM_TOTAL>>>(
        gh, gw2, go, bih, bhh, DH, DH / BK);

    // GEMM3: y = o @ W3^T + b3 -> fp32 row-major          (KT=32)
    gemm_f16_kernel<false, false><<<Mtiles * (DACT / BN), NTHR, SMEM_TOTAL>>>(
        go, gw3, out, b3, nullptr, DACT, DH / BK);

    (void)in_sizes; (void)n_in; (void)out_size;
}

// round 5
// speedup vs baseline: 2.6088x; 1.0107x over previous
#include <cuda_runtime.h>
#include <cuda_fp16.h>
#include <cstdint>

// ----------------------------------------------------------------------------
// fp16 mma.sync m16n8k16 + ldmatrix, cp.async.bulk (1D) + mbarrier pipeline.
// R5: producer moved AFTER compute (kills warp-0 empty-wait stall) and
// fragment double-buffering (ldsm of kk+1 overlaps mma of kk).
//
//   h = relu(x @ W_init^T + b_init)        M=32768 N=2048 K=1024
//   o = relu(h @ W_ih^T  + b_ih + b_hh)    M=32768 N=2048 K=2048
//   y =       o @ W_final^T + b_final      M=32768 N=1024 K=2048
//
// CTA tile 128x256, BK=64, 4-stage mbarrier pipeline, 8 warps (2Mx4N, 64x64).
// ----------------------------------------------------------------------------

#define DINLINE __device__ __forceinline__

static constexpr int DIN  = 1024;
static constexpr int DH   = 2048;
static constexpr int DACT = 1024;
static constexpr long MTOK = 32768;

static constexpr int BM = 128;
static constexpr int BN = 256;
static constexpr int BK = 64;            // 128B rows
static constexpr int STAGES = 4;
static constexpr int NTHR = 256;

static constexpr int A_ST = BM * BK * 2;         // 16384 B
static constexpr int B_ST = BN * BK * 2;         // 32768 B
static constexpr int STG  = A_ST + B_ST;         // 49152 B
static constexpr int HDR  = 1024;
static constexpr int SMEM_TOTAL = HDR + STAGES * STG;   // 197632

DINLINE uint32_t smem_u32(const void* p) {
    uint32_t a;
    asm("{ .reg .u64 t; cvta.to.shared.u64 t, %1; cvt.u32.u64 %0, t; }"
        : "=r"(a) : "l"(p));
    return a;
}

#define MBARRIER_INIT(addr, cnt) \
    asm volatile("mbarrier.init.shared.b64 [%0], %1;" :: "r"(addr), "r"(cnt) : "memory")
#define MBARRIER_ARRIVE(addr) \
    asm volatile("mbarrier.arrive.shared.b64 _, [%0];" :: "r"(addr) : "memory")
#define MBARRIER_EXPECT_TX(addr, n) \
    asm volatile("mbarrier.arrive.expect_tx.shared.b64 _, [%0], %1;" :: "r"(addr), "r"(n) : "memory")

#define MBARRIER_WAIT_PARITY(mbar_smem_addr, phase_parity) do { \
    uint32_t _mbar = (uint32_t)(mbar_smem_addr); \
    uint32_t _parity = (uint32_t)(phase_parity); \
    uint32_t _done; \
    asm volatile( \
        "{\n\t" \
        ".reg .pred p;\n\t" \
        "mbarrier.try_wait.parity.shared.b64 p, [%1], %2;\n\t" \
        "selp.b32 %0, 1, 0, p;\n\t" \
        "}" \
        : "=r"(_done) : "r"(_mbar), "r"(_parity) : "memory"); \
    if (!_done) { \
        asm volatile( \
            "{\n\t" \
            ".reg .pred P1;\n\t" \
            "WAIT_LOOP_%=:\n\t" \
            "mbarrier.try_wait.parity.shared.b64 P1, [%0], %1, 0x989680;\n\t" \
            "@P1 bra.uni WAIT_DONE_%=;\n\t" \
            "bra.uni WAIT_LOOP_%=;\n\t" \
            "WAIT_DONE_%=:\n\t" \
            "}" \
            :: "r"(_mbar), "r"(_parity) : "memory"); \
    } \
} while(0)

#define BULK_G2S(dst, src, sz, mbar) \
    asm volatile("cp.async.bulk.shared::cta.global.mbarrier::complete_tx::bytes [%0], [%1], %2, [%3];" \
        :: "r"((uint32_t)(dst)), "l"(src), "r"((uint32_t)(sz)), "r"((uint32_t)(mbar)) : "memory")

DINLINE void ldsm_x4(uint32_t* r, uint32_t addr) {
    asm volatile("ldmatrix.sync.aligned.m8n8.x4.shared.b16 {%0,%1,%2,%3}, [%4];"
        : "=r"(r[0]), "=r"(r[1]), "=r"(r[2]), "=r"(r[3]) : "r"(addr));
}

DINLINE void mma_f16(float* c, const uint32_t* a, const uint32_t* b) {
    asm volatile(
        "mma.sync.aligned.m16n8k16.row.col.f32.f16.f16.f32 "
        "{%0,%1,%2,%3}, {%4,%5,%6,%7}, {%8,%9}, {%0,%1,%2,%3};"
        : "+f"(c[0]), "+f"(c[1]), "+f"(c[2]), "+f"(c[3])
        : "r"(a[0]), "r"(a[1]), "r"(a[2]), "r"(a[3]), "r"(b[0]), "r"(b[1]));
}

// ----------------------------------------------------------------------------
// Scratch (static device allocations -- allowed). All in swizzled panel layout.
// ----------------------------------------------------------------------------
__device__ __half g_x [MTOK * DIN];
__device__ __half g_h [MTOK * DH];
__device__ __half g_o [MTOK * DH];
__device__ __half g_w1[(long)DH * DIN];
__device__ __half g_w2[(long)DH * DH];
__device__ __half g_w3[(long)DACT * DH];

// ----------------------------------------------------------------------------
// fp32 -> fp16 + tile/swizzle pre-pass.
// Panel layout (RP = 128 for A-operands, 256 for B-operands):
//   panel (r/RP, c/64), within: row (r%RP) of 8 granules (16B each),
//   granule index swizzled: g' = g ^ (r&7).
// ----------------------------------------------------------------------------
template <int RP>
__global__ void cvt_tile_kernel(const float* __restrict__ in, __half* __restrict__ out,
                                int kshift /* log2(K/8) */, int ng) {
    int gi = blockIdx.x * blockDim.x + threadIdx.x;
    if (gi >= ng) return;
    const int gperrow = 1 << kshift;
    const int c8 = gi & (gperrow - 1);
    const int r  = gi >> kshift;
    const float4* f4 = reinterpret_cast<const float4*>(in);
    float4 v0 = f4[2 * (size_t)gi], v1 = f4[2 * (size_t)gi + 1];
    __half2 h0 = __floats2half2_rn(v0.x, v0.y), h1 = __floats2half2_rn(v0.z, v0.w);
    __half2 h2 = __floats2half2_rn(v1.x, v1.y), h3 = __floats2half2_rn(v1.z, v1.w);
    uint4 o = make_uint4(*reinterpret_cast<uint32_t*>(&h0), *reinterpret_cast<uint32_t*>(&h1),
                         *reinterpret_cast<uint32_t*>(&h2), *reinterpret_cast<uint32_t*>(&h3));
    const size_t panel = (size_t)(r / RP) * (gperrow >> 3) + (c8 >> 3);
    const size_t gip   = (size_t)(r % RP) * 8 + ((c8 & 7) ^ (r & 7));
    reinterpret_cast<uint4*>(out)[panel * (RP * 8) + gip] = o;
}

// ----------------------------------------------------------------------------
// GEMM: C = act(A @ B^T + bias1 (+bias2)); A,B in swizzled panels.
// HALF_OUT -> write C as swizzled 128-row panels (next GEMM's A); else fp32 row-major.
// ----------------------------------------------------------------------------
template <bool HALF_OUT, bool RELU>
__global__ void __launch_bounds__(NTHR, 1)
gemm_f16_kernel(const __half* __restrict__ A, const __half* __restrict__ Bw,
                void* __restrict__ Cv,
                const float* __restrict__ bias1, const float* __restrict__ bias2,
                int N, int KT)
{
    extern __shared__ char smem[];
    const uint32_t sbase = smem_u32(smem);
    const int tid = threadIdx.x;
    const int wid = tid >> 5;
    const int lid = tid & 31;
    const int g   = lid >> 2;
    const int tg  = lid & 3;

    const int ntiles = N / BN;
    const int nt = blockIdx.x % ntiles;
    const int mt = blockIdx.x / ntiles;
    const long m0 = (long)mt * BM;
    const int  n0 = nt * BN;

    const int warpM = wid >> 2;
    const int warpN = wid & 3;

    // mbarriers: full[s] @ 8s, empty[s] @ 64+8s
    if (tid == 0) {
        #pragma unroll
        for (int s = 0; s < STAGES; ++s) {
            MBARRIER_INIT(sbase + 8 * s, 1);
            MBARRIER_INIT(sbase + 64 + 8 * s, 8);
        }
    }
    __syncthreads();

    const __half* aPan = A  + (size_t)mt * KT * (A_ST / 2);
    const __half* bPan = Bw + (size_t)nt * KT * (B_ST / 2);

    // prologue: fill stages 0..STAGES-2
    if (tid == 0) {
        #pragma unroll
        for (int s = 0; s < STAGES - 1; ++s) {
            const uint32_t st = sbase + HDR + s * STG;
            MBARRIER_EXPECT_TX(sbase + 8 * s, STG);
            BULK_G2S(st,        aPan + (size_t)s * (A_ST / 2), A_ST, sbase + 8 * s);
            BULK_G2S(st + A_ST, bPan + (size_t)s * (B_ST / 2), B_ST, sbase + 8 * s);
        }
    }

    float acc[4][8][4];
    #pragma unroll
    for (int i = 0; i < 4; ++i)
        #pragma unroll
        for (int j = 0; j < 8; ++j)
            #pragma unroll
            for (int e = 0; e < 4; ++e) acc[i][j][e] = 0.0f;

    // ldmatrix per-lane bases (swizzled granule addressing)
    const int lm   = lid >> 3;
    const int aRow = warpM * 64 + ((lm & 1) << 3) + (lid & 7);
    const int asel = lm >> 1;
    const int aXor = aRow & 7;
    const int bRow = warpN * 64 + ((lm >> 1) << 3) + (lid & 7);
    const int bsel = lm & 1;
    const int bXor = bRow & 7;
    uint32_t aBase[4], bBase[4];
    #pragma unroll
    for (int i = 0; i < 4; ++i) aBase[i] = (uint32_t)(aRow + i * 16) * 128;
    #pragma unroll
    for (int jp = 0; jp < 4; ++jp) bBase[jp] = (uint32_t)(bRow + jp * 16) * 128;

    for (int kt = 0; kt < KT; ++kt) {
        const int s = kt & (STAGES - 1);

        MBARRIER_WAIT_PARITY(sbase + 8 * s, (kt >> 2) & 1);

        const uint32_t sA = sbase + HDR + s * STG;
        const uint32_t sB = sA + A_ST;

        // double-buffered fragments: load kk+1 while mma'ing kk
        uint32_t fa[2][4][4], fb[2][4][4];

        {   // kk = 0 preload
            const uint32_t aoff = (uint32_t)(((0 + asel) ^ aXor) << 4);
            const uint32_t boff = (uint32_t)(((0 + bsel) ^ bXor) << 4);
            #pragma unroll
            for (int i = 0; i < 4; ++i)    ldsm_x4(fa[0][i],  sA + aBase[i]  + aoff);
            #pragma unroll
            for (int jp = 0; jp < 4; ++jp) ldsm_x4(fb[0][jp], sB + bBase[jp] + boff);
        }

        #pragma unroll
        for (int kk = 0; kk < 4; ++kk) {
            const int cur = kk & 1, nxt = cur ^ 1;
            if (kk < 3) {
                const uint32_t aoff = (uint32_t)((((kk + 1) * 2 + asel) ^ aXor) << 4);
                const uint32_t boff = (uint32_t)((((kk + 1) * 2 + bsel) ^ bXor) << 4);
                #pragma unroll
                for (int i = 0; i < 4; ++i)    ldsm_x4(fa[nxt][i],  sA + aBase[i]  + aoff);
                #pragma unroll
                for (int jp = 0; jp < 4; ++jp) ldsm_x4(fb[nxt][jp], sB + bBase[jp] + boff);
            }
            #pragma unroll
            for (int i = 0; i < 4; ++i)
                #pragma unroll
                for (int j = 0; j < 8; ++j)
                    mma_f16(acc[i][j], fa[cur][i], &fb[cur][j >> 1][(j & 1) * 2]);
        }

        // producer AFTER compute: refill stage (kt + STAGES-1).
        // empty[s2] needs 8 arrivals from iter kt-1; every warp reaching iter kt
        // has already arrived for kt-1, so this wait is (nearly) free.
        const int f = kt + STAGES - 1;
        if (tid == 0 && f < KT) {
            const int s2 = f & (STAGES - 1);
            if (f >= STAGES)
                MBARRIER_WAIT_PARITY(sbase + 64 + 8 * s2, ((f >> 2) - 1) & 1);
            const uint32_t st = sbase + HDR + s2 * STG;
            MBARRIER_EXPECT_TX(sbase + 8 * s2, STG);
            BULK_G2S(st,        aPan + (size_t)f * (A_ST / 2), A_ST, sbase + 8 * s2);
            BULK_G2S(st + A_ST, bPan + (size_t)f * (B_ST / 2), B_ST, sbase + 8 * s2);
        }

        __syncwarp();
        if (lid == 0) MBARRIER_ARRIVE(sbase + 64 + 8 * s);
    }

    // ---- epilogue ----------------------------------------------------------
    const bool has2 = (bias2 != nullptr);
    const int jb0 = n0 + warpN * 64;

    #pragma unroll
    for (int j = 0; j < 8; ++j) {
        const int col = jb0 + j * 8 + 2 * tg;
        float bb0 = bias1[col], bb1 = bias1[col + 1];
        if (has2) { bb0 += bias2[col]; bb1 += bias2[col + 1]; }
        #pragma unroll
        for (int i = 0; i < 4; ++i) {
            const long r0 = m0 + warpM * 64 + i * 16 + g;
            #pragma unroll
            for (int h = 0; h < 2; ++h) {
                const long r = r0 + 8 * h;
                float v0 = acc[i][j][2 * h + 0] + bb0;
                float v1 = acc[i][j][2 * h + 1] + bb1;
                if (RELU) { v0 = fmaxf(v0, 0.0f); v1 = fmaxf(v1, 0.0f); }
                if (HALF_OUT) {
                    // swizzled 128-row panel layout (next GEMM's A operand)
                    __half2 hv = __floats2half2_rn(v0, v1);
                    const size_t panel = ((size_t)(r >> 7) * (N >> 6) + (col >> 6)) << 13;
                    const size_t off = panel + (size_t)((int)(r & 127)) * 64
                                     + (size_t)(((((col >> 3) & 7) ^ ((int)r & 7)) << 3) + (col & 7));
                    *reinterpret_cast<uint32_t*>((__half*)Cv + off) =
                        *reinterpret_cast<uint32_t*>(&hv);
                } else {
                    *reinterpret_cast<float2*>((float*)Cv + (size_t)r * N + col) =
                        make_float2(v0, v1);
                }
            }
        }
    }
}

// ----------------------------------------------------------------------------
// Host launcher
// ----------------------------------------------------------------------------
extern "C" void kernel_launch(void* const* d_in, const int* in_sizes, int n_in,
                              void* d_out, int out_size)
{
    const float* x    = (const float*)d_in[0];
    const float* W1   = (const float*)d_in[1];
    const float* b1   = (const float*)d_in[2];
    const float* W2   = (const float*)d_in[3];
    const float* bih  = (const float*)d_in[4];
    const float* bhh  = (const float*)d_in[5];
    const float* W3   = (const float*)d_in[6];
    const float* b3   = (const float*)d_in[7];
    float* out = (float*)d_out;

    __half *gx, *gh, *go, *gw1, *gw2, *gw3;
    cudaGetSymbolAddress((void**)&gx,  g_x);
    cudaGetSymbolAddress((void**)&gh,  g_h);
    cudaGetSymbolAddress((void**)&go,  g_o);
    cudaGetSymbolAddress((void**)&gw1, g_w1);
    cudaGetSymbolAddress((void**)&gw2, g_w2);
    cudaGetSymbolAddress((void**)&gw3, g_w3);

    cudaFuncSetAttribute(gemm_f16_kernel<true, true>,
                         cudaFuncAttributeMaxDynamicSharedMemorySize, SMEM_TOTAL);
    cudaFuncSetAttribute(gemm_f16_kernel<false, false>,
                         cudaFuncAttributeMaxDynamicSharedMemorySize, SMEM_TOTAL);

    // pre-pass: fp32 -> fp16 into swizzled panels
    {
        int ng;
        ng = (int)(MTOK * (long)DIN / 8);              // x: RP=128, K=1024
        cvt_tile_kernel<128><<<(ng + 255) / 256, 256>>>(x, gx, 7, ng);
        ng = (int)((long)DH * DIN / 8);                // W1: RP=256, K=1024
        cvt_tile_kernel<256><<<(ng + 255) / 256, 256>>>(W1, gw1, 7, ng);
        ng = (int)((long)DH * DH / 8);                 // W2: RP=256, K=2048
        cvt_tile_kernel<256><<<(ng + 255) / 256, 256>>>(W2, gw2, 8, ng);
        ng = (int)((long)DACT * DH / 8);               // W3: RP=256, K=2048
        cvt_tile_kernel<256><<<(ng + 255) / 256, 256>>>(W3, gw3, 8, ng);
    }

    const int Mtiles = (int)(MTOK / BM);   // 256

    // GEMM1: h = relu(x @ W1^T + b1) -> fp16 panels      (KT=16)
    gemm_f16_kernel<true, true><<<Mtiles * (DH / BN), NTHR, SMEM_TOTAL>>>(
        gx, gw1, gh, b1, nullptr, DH, DIN / BK);

    // GEMM2: o = relu(h @ W2^T + bih + bhh) -> fp16 panels (KT=32)
    gemm_f16_kernel<true, true><<<Mtiles * (DH / BN), NTHR, SMEM_TOTAL>>>(
        gh, gw2, go, bih, bhh, DH, DH / BK);

    // GEMM3: y = o @ W3^T + b3 -> fp32 row-major          (KT=32)
    gemm_f16_kernel<false, false><<<Mtiles * (DACT / BN), NTHR, SMEM_TOTAL>>>(
        go, gw3, out, b3, nullptr, DACT, DH / BK);

    (void)in_sizes; (void)n_in; (void)out_size;
}

// round 6
// speedup vs baseline: 2.6188x; 1.0038x over previous
#include <cuda_runtime.h>
#include <cuda_fp16.h>
#include <cstdint>

// ----------------------------------------------------------------------------
// fp16 mma.sync m16n8k16 + ldmatrix, cp.async.bulk (1D) + mbarrier pipeline.
// R6: all four fp32->fp16 panel-conversion launches fused into ONE grid-stride
// kernel (saves launch overhead, saturates DRAM, and shifts ncu's -s 5 window
// onto a GEMM launch for the next round's profile).
//
//   h = relu(x @ W_init^T + b_init)        M=32768 N=2048 K=1024
//   o = relu(h @ W_ih^T  + b_ih + b_hh)    M=32768 N=2048 K=2048
//   y =       o @ W_final^T + b_final      M=32768 N=1024 K=2048
//
// CTA tile 128x256, BK=64, 4-stage mbarrier pipeline, 8 warps (2Mx4N, 64x64).
// ----------------------------------------------------------------------------

#define DINLINE __device__ __forceinline__

static constexpr int DIN  = 1024;
static constexpr int DH   = 2048;
static constexpr int DACT = 1024;
static constexpr long MTOK = 32768;

static constexpr int BM = 128;
static constexpr int BN = 256;
static constexpr int BK = 64;            // 128B rows
static constexpr int STAGES = 4;
static constexpr int NTHR = 256;

static constexpr int A_ST = BM * BK * 2;         // 16384 B
static constexpr int B_ST = BN * BK * 2;         // 32768 B
static constexpr int STG  = A_ST + B_ST;         // 49152 B
static constexpr int HDR  = 1024;
static constexpr int SMEM_TOTAL = HDR + STAGES * STG;   // 197632

DINLINE uint32_t smem_u32(const void* p) {
    uint32_t a;
    asm("{ .reg .u64 t; cvta.to.shared.u64 t, %1; cvt.u32.u64 %0, t; }"
        : "=r"(a) : "l"(p));
    return a;
}

#define MBARRIER_INIT(addr, cnt) \
    asm volatile("mbarrier.init.shared.b64 [%0], %1;" :: "r"(addr), "r"(cnt) : "memory")
#define MBARRIER_ARRIVE(addr) \
    asm volatile("mbarrier.arrive.shared.b64 _, [%0];" :: "r"(addr) : "memory")
#define MBARRIER_EXPECT_TX(addr, n) \
    asm volatile("mbarrier.arrive.expect_tx.shared.b64 _, [%0], %1;" :: "r"(addr), "r"(n) : "memory")

#define MBARRIER_WAIT_PARITY(mbar_smem_addr, phase_parity) do { \
    uint32_t _mbar = (uint32_t)(mbar_smem_addr); \
    uint32_t _parity = (uint32_t)(phase_parity); \
    uint32_t _done; \
    asm volatile( \
        "{\n\t" \
        ".reg .pred p;\n\t" \
        "mbarrier.try_wait.parity.shared.b64 p, [%1], %2;\n\t" \
        "selp.b32 %0, 1, 0, p;\n\t" \
        "}" \
        : "=r"(_done) : "r"(_mbar), "r"(_parity) : "memory"); \
    if (!_done) { \
        asm volatile( \
            "{\n\t" \
            ".reg .pred P1;\n\t" \
            "WAIT_LOOP_%=:\n\t" \
            "mbarrier.try_wait.parity.shared.b64 P1, [%0], %1, 0x989680;\n\t" \
            "@P1 bra.uni WAIT_DONE_%=;\n\t" \
            "bra.uni WAIT_LOOP_%=;\n\t" \
            "WAIT_DONE_%=:\n\t" \
            "}" \
            :: "r"(_mbar), "r"(_parity) : "memory"); \
    } \
} while(0)

#define BULK_G2S(dst, src, sz, mbar) \
    asm volatile("cp.async.bulk.shared::cta.global.mbarrier::complete_tx::bytes [%0], [%1], %2, [%3];" \
        :: "r"((uint32_t)(dst)), "l"(src), "r"((uint32_t)(sz)), "r"((uint32_t)(mbar)) : "memory")

DINLINE void ldsm_x4(uint32_t* r, uint32_t addr) {
    asm volatile("ldmatrix.sync.aligned.m8n8.x4.shared.b16 {%0,%1,%2,%3}, [%4];"
        : "=r"(r[0]), "=r"(r[1]), "=r"(r[2]), "=r"(r[3]) : "r"(addr));
}

DINLINE void mma_f16(float* c, const uint32_t* a, const uint32_t* b) {
    asm volatile(
        "mma.sync.aligned.m16n8k16.row.col.f32.f16.f16.f32 "
        "{%0,%1,%2,%3}, {%4,%5,%6,%7}, {%8,%9}, {%0,%1,%2,%3};"
        : "+f"(c[0]), "+f"(c[1]), "+f"(c[2]), "+f"(c[3])
        : "r"(a[0]), "r"(a[1]), "r"(a[2]), "r"(a[3]), "r"(b[0]), "r"(b[1]));
}

// ----------------------------------------------------------------------------
// Scratch (static device allocations -- allowed). All in swizzled panel layout.
// ----------------------------------------------------------------------------
__device__ __half g_x [MTOK * DIN];
__device__ __half g_h [MTOK * DH];
__device__ __half g_o [MTOK * DH];
__device__ __half g_w1[(long)DH * DIN];
__device__ __half g_w2[(long)DH * DH];
__device__ __half g_w3[(long)DACT * DH];

// ----------------------------------------------------------------------------
// Fused fp32 -> fp16 + tile/swizzle pre-pass (all four tensors, one launch).
// Panel layout (RP = 128 for A-operands, 256 for B-operands):
//   panel (r/RP, c/64), within: row (r%RP) of 8 granules (16B each),
//   granule index swizzled: g' = g ^ (r&7). One granule = 16B out, 32B in.
// ----------------------------------------------------------------------------
struct CvtSeg {
    const float* in;
    __half* out;
    int ng;        // granule count
    int kshift;    // log2(K/8)
    int rplog;     // log2(RP)
};

__global__ void __launch_bounds__(512, 2)
cvt_all_kernel(CvtSeg s0, CvtSeg s1, CvtSeg s2, CvtSeg s3, int total)
{
    for (int gi0 = blockIdx.x * blockDim.x + threadIdx.x; gi0 < total;
         gi0 += gridDim.x * blockDim.x) {
        CvtSeg s; int gi = gi0;
        if (gi < s0.ng) s = s0;
        else {
            gi -= s0.ng;
            if (gi < s1.ng) s = s1;
            else {
                gi -= s1.ng;
                if (gi < s2.ng) s = s2;
                else { gi -= s2.ng; s = s3; }
            }
        }
        const int gperrow = 1 << s.kshift;
        const int c8 = gi & (gperrow - 1);
        const int r  = gi >> s.kshift;
        const float4* f4 = reinterpret_cast<const float4*>(s.in);
        float4 v0 = f4[2 * (size_t)gi], v1 = f4[2 * (size_t)gi + 1];
        __half2 h0 = __floats2half2_rn(v0.x, v0.y), h1 = __floats2half2_rn(v0.z, v0.w);
        __half2 h2 = __floats2half2_rn(v1.x, v1.y), h3 = __floats2half2_rn(v1.z, v1.w);
        uint4 o = make_uint4(*reinterpret_cast<uint32_t*>(&h0), *reinterpret_cast<uint32_t*>(&h1),
                             *reinterpret_cast<uint32_t*>(&h2), *reinterpret_cast<uint32_t*>(&h3));
        const int rp = 1 << s.rplog;
        const size_t panel = (size_t)(r >> s.rplog) * (gperrow >> 3) + (c8 >> 3);
        const size_t gip   = (size_t)(r & (rp - 1)) * 8 + ((c8 & 7) ^ (r & 7));
        reinterpret_cast<uint4*>(s.out)[panel * ((size_t)rp * 8) + gip] = o;
    }
}

// ----------------------------------------------------------------------------
// GEMM: C = act(A @ B^T + bias1 (+bias2)); A,B in swizzled panels.
// HALF_OUT -> write C as swizzled 128-row panels (next GEMM's A); else fp32 row-major.
// ----------------------------------------------------------------------------
template <bool HALF_OUT, bool RELU>
__global__ void __launch_bounds__(NTHR, 1)
gemm_f16_kernel(const __half* __restrict__ A, const __half* __restrict__ Bw,
                void* __restrict__ Cv,
                const float* __restrict__ bias1, const float* __restrict__ bias2,
                int N, int KT)
{
    extern __shared__ char smem[];
    const uint32_t sbase = smem_u32(smem);
    const int tid = threadIdx.x;
    const int wid = tid >> 5;
    const int lid = tid & 31;
    const int g   = lid >> 2;
    const int tg  = lid & 3;

    const int ntiles = N / BN;
    const int nt = blockIdx.x % ntiles;
    const int mt = blockIdx.x / ntiles;
    const long m0 = (long)mt * BM;
    const int  n0 = nt * BN;

    const int warpM = wid >> 2;
    const int warpN = wid & 3;

    // mbarriers: full[s] @ 8s, empty[s] @ 64+8s
    if (tid == 0) {
        #pragma unroll
        for (int s = 0; s < STAGES; ++s) {
            MBARRIER_INIT(sbase + 8 * s, 1);
            MBARRIER_INIT(sbase + 64 + 8 * s, 8);
        }
    }
    __syncthreads();

    const __half* aPan = A  + (size_t)mt * KT * (A_ST / 2);
    const __half* bPan = Bw + (size_t)nt * KT * (B_ST / 2);

    // prologue: fill stages 0..STAGES-2
    if (tid == 0) {
        #pragma unroll
        for (int s = 0; s < STAGES - 1; ++s) {
            const uint32_t st = sbase + HDR + s * STG;
            MBARRIER_EXPECT_TX(sbase + 8 * s, STG);
            BULK_G2S(st,        aPan + (size_t)s * (A_ST / 2), A_ST, sbase + 8 * s);
            BULK_G2S(st + A_ST, bPan + (size_t)s * (B_ST / 2), B_ST, sbase + 8 * s);
        }
    }

    float acc[4][8][4];
    #pragma unroll
    for (int i = 0; i < 4; ++i)
        #pragma unroll
        for (int j = 0; j < 8; ++j)
            #pragma unroll
            for (int e = 0; e < 4; ++e) acc[i][j][e] = 0.0f;

    // ldmatrix per-lane bases (swizzled granule addressing)
    const int lm   = lid >> 3;
    const int aRow = warpM * 64 + ((lm & 1) << 3) + (lid & 7);
    const int asel = lm >> 1;
    const int aXor = aRow & 7;
    const int bRow = warpN * 64 + ((lm >> 1) << 3) + (lid & 7);
    const int bsel = lm & 1;
    const int bXor = bRow & 7;
    uint32_t aBase[4], bBase[4];
    #pragma unroll
    for (int i = 0; i < 4; ++i) aBase[i] = (uint32_t)(aRow + i * 16) * 128;
    #pragma unroll
    for (int jp = 0; jp < 4; ++jp) bBase[jp] = (uint32_t)(bRow + jp * 16) * 128;

    for (int kt = 0; kt < KT; ++kt) {
        const int s = kt & (STAGES - 1);

        MBARRIER_WAIT_PARITY(sbase + 8 * s, (kt >> 2) & 1);

        const uint32_t sA = sbase + HDR + s * STG;
        const uint32_t sB = sA + A_ST;

        // double-buffered fragments: load kk+1 while mma'ing kk
        uint32_t fa[2][4][4], fb[2][4][4];

        {   // kk = 0 preload
            const uint32_t aoff = (uint32_t)(((0 + asel) ^ aXor) << 4);
            const uint32_t boff = (uint32_t)(((0 + bsel) ^ bXor) << 4);
            #pragma unroll
            for (int i = 0; i < 4; ++i)    ldsm_x4(fa[0][i],  sA + aBase[i]  + aoff);
            #pragma unroll
            for (int jp = 0; jp < 4; ++jp) ldsm_x4(fb[0][jp], sB + bBase[jp] + boff);
        }

        #pragma unroll
        for (int kk = 0; kk < 4; ++kk) {
            const int cur = kk & 1, nxt = cur ^ 1;
            if (kk < 3) {
                const uint32_t aoff = (uint32_t)((((kk + 1) * 2 + asel) ^ aXor) << 4);
                const uint32_t boff = (uint32_t)((((kk + 1) * 2 + bsel) ^ bXor) << 4);
                #pragma unroll
                for (int i = 0; i < 4; ++i)    ldsm_x4(fa[nxt][i],  sA + aBase[i]  + aoff);
                #pragma unroll
                for (int jp = 0; jp < 4; ++jp) ldsm_x4(fb[nxt][jp], sB + bBase[jp] + boff);
            }
            #pragma unroll
            for (int i = 0; i < 4; ++i)
                #pragma unroll
                for (int j = 0; j < 8; ++j)
                    mma_f16(acc[i][j], fa[cur][i], &fb[cur][j >> 1][(j & 1) * 2]);
        }

        // producer AFTER compute: refill stage (kt + STAGES-1).
        const int f = kt + STAGES - 1;
        if (tid == 0 && f < KT) {
            const int s2 = f & (STAGES - 1);
            if (f >= STAGES)
                MBARRIER_WAIT_PARITY(sbase + 64 + 8 * s2, ((f >> 2) - 1) & 1);
            const uint32_t st = sbase + HDR + s2 * STG;
            MBARRIER_EXPECT_TX(sbase + 8 * s2, STG);
            BULK_G2S(st,        aPan + (size_t)f * (A_ST / 2), A_ST, sbase + 8 * s2);
            BULK_G2S(st + A_ST, bPan + (size_t)f * (B_ST / 2), B_ST, sbase + 8 * s2);
        }

        __syncwarp();
        if (lid == 0) MBARRIER_ARRIVE(sbase + 64 + 8 * s);
    }

    // ---- epilogue ----------------------------------------------------------
    const bool has2 = (bias2 != nullptr);
    const int jb0 = n0 + warpN * 64;

    #pragma unroll
    for (int j = 0; j < 8; ++j) {
        const int col = jb0 + j * 8 + 2 * tg;
        float bb0 = bias1[col], bb1 = bias1[col + 1];
        if (has2) { bb0 += bias2[col]; bb1 += bias2[col + 1]; }
        #pragma unroll
        for (int i = 0; i < 4; ++i) {
            const long r0 = m0 + warpM * 64 + i * 16 + g;
            #pragma unroll
            for (int h = 0; h < 2; ++h) {
                const long r = r0 + 8 * h;
                float v0 = acc[i][j][2 * h + 0] + bb0;
                float v1 = acc[i][j][2 * h + 1] + bb1;
                if (RELU) { v0 = fmaxf(v0, 0.0f); v1 = fmaxf(v1, 0.0f); }
                if (HALF_OUT) {
                    // swizzled 128-row panel layout (next GEMM's A operand)
                    __half2 hv = __floats2half2_rn(v0, v1);
                    const size_t panel = ((size_t)(r >> 7) * (N >> 6) + (col >> 6)) << 13;
                    const size_t off = panel + (size_t)((int)(r & 127)) * 64
                                     + (size_t)(((((col >> 3) & 7) ^ ((int)r & 7)) << 3) + (col & 7));
                    *reinterpret_cast<uint32_t*>((__half*)Cv + off) =
                        *reinterpret_cast<uint32_t*>(&hv);
                } else {
                    *reinterpret_cast<float2*>((float*)Cv + (size_t)r * N + col) =
                        make_float2(v0, v1);
                }
            }
        }
    }
}

// ----------------------------------------------------------------------------
// Host launcher
// ----------------------------------------------------------------------------
extern "C" void kernel_launch(void* const* d_in, const int* in_sizes, int n_in,
                              void* d_out, int out_size)
{
    const float* x    = (const float*)d_in[0];
    const float* W1   = (const float*)d_in[1];
    const float* b1   = (const float*)d_in[2];
    const float* W2   = (const float*)d_in[3];
    const float* bih  = (const float*)d_in[4];
    const float* bhh  = (const float*)d_in[5];
    const float* W3   = (const float*)d_in[6];
    const float* b3   = (const float*)d_in[7];
    float* out = (float*)d_out;

    __half *gx, *gh, *go, *gw1, *gw2, *gw3;
    cudaGetSymbolAddress((void**)&gx,  g_x);
    cudaGetSymbolAddress((void**)&gh,  g_h);
    cudaGetSymbolAddress((void**)&go,  g_o);
    cudaGetSymbolAddress((void**)&gw1, g_w1);
    cudaGetSymbolAddress((void**)&gw2, g_w2);
    cudaGetSymbolAddress((void**)&gw3, g_w3);

    cudaFuncSetAttribute(gemm_f16_kernel<true, true>,
                         cudaFuncAttributeMaxDynamicSharedMemorySize, SMEM_TOTAL);
    cudaFuncSetAttribute(gemm_f16_kernel<false, false>,
                         cudaFuncAttributeMaxDynamicSharedMemorySize, SMEM_TOTAL);

    // fused pre-pass: fp32 -> fp16 into swizzled panels (single launch)
    {
        CvtSeg s0 = { x,  gx,  (int)(MTOK * (long)DIN / 8), 7, 7 };   // RP=128
        CvtSeg s1 = { W1, gw1, (int)((long)DH * DIN / 8),   7, 8 };   // RP=256
        CvtSeg s2 = { W2, gw2, (int)((long)DH * DH / 8),    8, 8 };
        CvtSeg s3 = { W3, gw3, (int)((long)DACT * DH / 8),  8, 8 };
        const int total = s0.ng + s1.ng + s2.ng + s3.ng;
        cvt_all_kernel<<<2048, 512>>>(s0, s1, s2, s3, total);
    }

    const int Mtiles = (int)(MTOK / BM);   // 256

    // GEMM1: h = relu(x @ W1^T + b1) -> fp16 panels      (KT=16)
    gemm_f16_kernel<true, true><<<Mtiles * (DH / BN), NTHR, SMEM_TOTAL>>>(
        gx, gw1, gh, b1, nullptr, DH, DIN / BK);

    // GEMM2: o = relu(h @ W2^T + bih + bhh) -> fp16 panels (KT=32)
    gemm_f16_kernel<true, true><<<Mtiles * (DH / BN), NTHR, SMEM_TOTAL>>>(
        gh, gw2, go, bih, bhh, DH, DH / BK);

    // GEMM3: y = o @ W3^T + b3 -> fp32 row-major          (KT=32)
    gemm_f16_kernel<false, false><<<Mtiles * (DACT / BN), NTHR, SMEM_TOTAL>>>(
        go, gw3, out, b3, nullptr, DACT, DH / BK);

    (void)in_sizes; (void)n_in; (void)out_size;
}

// round 7
// speedup vs baseline: 2.7096x; 1.0347x over previous
#include <cuda_runtime.h>
#include <cuda_fp16.h>
#include <cstdint>

// ----------------------------------------------------------------------------
// fp16 mma.sync m16n8k16 + ldmatrix, cp.async.bulk (1D) + mbarrier pipeline.
// R7: persistent CTAs (grid = #SMs). One continuous pipeline across all tiles
// of a CTA: producer prefetch crosses tile boundaries, so the refill bubble is
// hidden behind the previous tile's epilogue; per-CTA setup paid once per SM.
//
//   h = relu(x @ W_init^T + b_init)        M=32768 N=2048 K=1024
//   o = relu(h @ W_ih^T  + b_ih + b_hh)    M=32768 N=2048 K=2048
//   y =       o @ W_final^T + b_final      M=32768 N=1024 K=2048
//
// CTA tile 128x256, BK=64, 4-stage mbarrier pipeline, 8 warps (2Mx4N, 64x64).
// ----------------------------------------------------------------------------

#define DINLINE __device__ __forceinline__

static constexpr int DIN  = 1024;
static constexpr int DH   = 2048;
static constexpr int DACT = 1024;
static constexpr long MTOK = 32768;

static constexpr int BM = 128;
static constexpr int BN = 256;
static constexpr int BK = 64;            // 128B rows
static constexpr int STAGES = 4;
static constexpr int NTHR = 256;

static constexpr int A_ST = BM * BK * 2;         // 16384 B
static constexpr int B_ST = BN * BK * 2;         // 32768 B
static constexpr int STG  = A_ST + B_ST;         // 49152 B
static constexpr int HDR  = 1024;
static constexpr int SMEM_TOTAL = HDR + STAGES * STG;   // 197632

DINLINE uint32_t smem_u32(const void* p) {
    uint32_t a;
    asm("{ .reg .u64 t; cvta.to.shared.u64 t, %1; cvt.u32.u64 %0, t; }"
        : "=r"(a) : "l"(p));
    return a;
}

#define MBARRIER_INIT(addr, cnt) \
    asm volatile("mbarrier.init.shared.b64 [%0], %1;" :: "r"(addr), "r"(cnt) : "memory")
#define MBARRIER_ARRIVE(addr) \
    asm volatile("mbarrier.arrive.shared.b64 _, [%0];" :: "r"(addr) : "memory")
#define MBARRIER_EXPECT_TX(addr, n) \
    asm volatile("mbarrier.arrive.expect_tx.shared.b64 _, [%0], %1;" :: "r"(addr), "r"(n) : "memory")

#define MBARRIER_WAIT_PARITY(mbar_smem_addr, phase_parity) do { \
    uint32_t _mbar = (uint32_t)(mbar_smem_addr); \
    uint32_t _parity = (uint32_t)(phase_parity); \
    uint32_t _done; \
    asm volatile( \
        "{\n\t" \
        ".reg .pred p;\n\t" \
        "mbarrier.try_wait.parity.shared.b64 p, [%1], %2;\n\t" \
        "selp.b32 %0, 1, 0, p;\n\t" \
        "}" \
        : "=r"(_done) : "r"(_mbar), "r"(_parity) : "memory"); \
    if (!_done) { \
        asm volatile( \
            "{\n\t" \
            ".reg .pred P1;\n\t" \
            "WAIT_LOOP_%=:\n\t" \
            "mbarrier.try_wait.parity.shared.b64 P1, [%0], %1, 0x989680;\n\t" \
            "@P1 bra.uni WAIT_DONE_%=;\n\t" \
            "bra.uni WAIT_LOOP_%=;\n\t" \
            "WAIT_DONE_%=:\n\t" \
            "}" \
            :: "r"(_mbar), "r"(_parity) : "memory"); \
    } \
} while(0)

#define BULK_G2S(dst, src, sz, mbar) \
    asm volatile("cp.async.bulk.shared::cta.global.mbarrier::complete_tx::bytes [%0], [%1], %2, [%3];" \
        :: "r"((uint32_t)(dst)), "l"(src), "r"((uint32_t)(sz)), "r"((uint32_t)(mbar)) : "memory")

DINLINE void ldsm_x4(uint32_t* r, uint32_t addr) {
    asm volatile("ldmatrix.sync.aligned.m8n8.x4.shared.b16 {%0,%1,%2,%3}, [%4];"
        : "=r"(r[0]), "=r"(r[1]), "=r"(r[2]), "=r"(r[3]) : "r"(addr));
}

DINLINE void mma_f16(float* c, const uint32_t* a, const uint32_t* b) {
    asm volatile(
        "mma.sync.aligned.m16n8k16.row.col.f32.f16.f16.f32 "
        "{%0,%1,%2,%3}, {%4,%5,%6,%7}, {%8,%9}, {%0,%1,%2,%3};"
        : "+f"(c[0]), "+f"(c[1]), "+f"(c[2]), "+f"(c[3])
        : "r"(a[0]), "r"(a[1]), "r"(a[2]), "r"(a[3]), "r"(b[0]), "r"(b[1]));
}

// ----------------------------------------------------------------------------
// Scratch (static device allocations -- allowed). All in swizzled panel layout.
// ----------------------------------------------------------------------------
__device__ __half g_x [MTOK * DIN];
__device__ __half g_h [MTOK * DH];
__device__ __half g_o [MTOK * DH];
__device__ __half g_w1[(long)DH * DIN];
__device__ __half g_w2[(long)DH * DH];
__device__ __half g_w3[(long)DACT * DH];

// ----------------------------------------------------------------------------
// Fused fp32 -> fp16 + tile/swizzle pre-pass (all four tensors, one launch).
// ----------------------------------------------------------------------------
struct CvtSeg {
    const float* in;
    __half* out;
    int ng;        // granule count
    int kshift;    // log2(K/8)
    int rplog;     // log2(RP)
};

__global__ void __launch_bounds__(512, 2)
cvt_all_kernel(CvtSeg s0, CvtSeg s1, CvtSeg s2, CvtSeg s3, int total)
{
    for (int gi0 = blockIdx.x * blockDim.x + threadIdx.x; gi0 < total;
         gi0 += gridDim.x * blockDim.x) {
        CvtSeg s; int gi = gi0;
        if (gi < s0.ng) s = s0;
        else {
            gi -= s0.ng;
            if (gi < s1.ng) s = s1;
            else {
                gi -= s1.ng;
                if (gi < s2.ng) s = s2;
                else { gi -= s2.ng; s = s3; }
            }
        }
        const int gperrow = 1 << s.kshift;
        const int c8 = gi & (gperrow - 1);
        const int r  = gi >> s.kshift;
        const float4* f4 = reinterpret_cast<const float4*>(s.in);
        float4 v0 = f4[2 * (size_t)gi], v1 = f4[2 * (size_t)gi + 1];
        __half2 h0 = __floats2half2_rn(v0.x, v0.y), h1 = __floats2half2_rn(v0.z, v0.w);
        __half2 h2 = __floats2half2_rn(v1.x, v1.y), h3 = __floats2half2_rn(v1.z, v1.w);
        uint4 o = make_uint4(*reinterpret_cast<uint32_t*>(&h0), *reinterpret_cast<uint32_t*>(&h1),
                             *reinterpret_cast<uint32_t*>(&h2), *reinterpret_cast<uint32_t*>(&h3));
        const int rp = 1 << s.rplog;
        const size_t panel = (size_t)(r >> s.rplog) * (gperrow >> 3) + (c8 >> 3);
        const size_t gip   = (size_t)(r & (rp - 1)) * 8 + ((c8 & 7) ^ (r & 7));
        reinterpret_cast<uint4*>(s.out)[panel * ((size_t)rp * 8) + gip] = o;
    }
}

// ----------------------------------------------------------------------------
// Persistent GEMM: C = act(A @ B^T + bias1 (+bias2)); A,B in swizzled panels.
// Tiles assigned tile = bid + i*gridDim.x; one continuous mbarrier pipeline.
// HALF_OUT -> write C as swizzled 128-row panels (next GEMM's A); else fp32.
// ----------------------------------------------------------------------------
template <bool HALF_OUT, bool RELU>
__global__ void __launch_bounds__(NTHR, 1)
gemm_f16_kernel(const __half* __restrict__ A, const __half* __restrict__ Bw,
                void* __restrict__ Cv,
                const float* __restrict__ bias1, const float* __restrict__ bias2,
                int N, int ktlog, int ntlog, int Ttiles)
{
    extern __shared__ char smem[];
    const uint32_t sbase = smem_u32(smem);
    const int tid = threadIdx.x;
    const int wid = tid >> 5;
    const int lid = tid & 31;
    const int g   = lid >> 2;
    const int tg  = lid & 3;
    const int bid = blockIdx.x;
    const int grid = gridDim.x;
    const int KT = 1 << ktlog;
    const int ntmask = (1 << ntlog) - 1;

    const int warpM = wid >> 2;
    const int warpN = wid & 3;

    // mbarriers: full[s] @ 8s, empty[s] @ 64+8s
    if (tid == 0) {
        #pragma unroll
        for (int s = 0; s < STAGES; ++s) {
            MBARRIER_INIT(sbase + 8 * s, 1);
            MBARRIER_INIT(sbase + 64 + 8 * s, 8);
        }
    }
    __syncthreads();

    const int nMy = (bid < Ttiles) ? ((Ttiles - bid - 1) / grid + 1) : 0;
    if (nMy == 0) return;
    const long totIt = (long)nMy << ktlog;

    // map global iteration q -> (A panel, B panel) source pointers
    auto panels = [&](long q, const __half*& pa, const __half*& pb) {
        const int tIdx = (int)(q >> ktlog);
        const int kt   = (int)(q & (KT - 1));
        const int tile = bid + tIdx * grid;
        const int mtq  = tile >> ntlog;
        const int ntq  = tile & ntmask;
        pa = A  + ((size_t)mtq * KT + kt) * (A_ST / 2);
        pb = Bw + ((size_t)ntq * KT + kt) * (B_ST / 2);
    };

    // prologue: fill first min(STAGES-1, totIt) stages
    if (tid == 0) {
        #pragma unroll
        for (int s = 0; s < STAGES - 1; ++s) {
            if (s < totIt) {
                const __half *pa, *pb;
                panels(s, pa, pb);
                const uint32_t st = sbase + HDR + s * STG;
                MBARRIER_EXPECT_TX(sbase + 8 * s, STG);
                BULK_G2S(st,        pa, A_ST, sbase + 8 * s);
                BULK_G2S(st + A_ST, pb, B_ST, sbase + 8 * s);
            }
        }
    }

    // ldmatrix per-lane bases (swizzled granule addressing)
    const int lm   = lid >> 3;
    const int aRow = warpM * 64 + ((lm & 1) << 3) + (lid & 7);
    const int asel = lm >> 1;
    const int aXor = aRow & 7;
    const int bRow = warpN * 64 + ((lm >> 1) << 3) + (lid & 7);
    const int bsel = lm & 1;
    const int bXor = bRow & 7;
    uint32_t aBase[4], bBase[4];
    #pragma unroll
    for (int i = 0; i < 4; ++i) aBase[i] = (uint32_t)(aRow + i * 16) * 128;
    #pragma unroll
    for (int jp = 0; jp < 4; ++jp) bBase[jp] = (uint32_t)(bRow + jp * 16) * 128;

    for (int tl = 0; tl < nMy; ++tl) {
        const int tile = bid + tl * grid;
        const int mt = tile >> ntlog;
        const int nt = tile & ntmask;
        const long m0 = (long)mt * BM;
        const int  n0 = nt * BN;
        const long gbase = (long)tl << ktlog;

        float acc[4][8][4];
        #pragma unroll
        for (int i = 0; i < 4; ++i)
            #pragma unroll
            for (int j = 0; j < 8; ++j)
                #pragma unroll
                for (int e = 0; e < 4; ++e) acc[i][j][e] = 0.0f;

        for (int kt = 0; kt < KT; ++kt) {
            const long gi = gbase + kt;
            const int s = (int)(gi & (STAGES - 1));

            MBARRIER_WAIT_PARITY(sbase + 8 * s, (uint32_t)((gi >> 2) & 1));

            const uint32_t sA = sbase + HDR + s * STG;
            const uint32_t sB = sA + A_ST;

            // double-buffered fragments: load kk+1 while mma'ing kk
            uint32_t fa[2][4][4], fb[2][4][4];
            {   // kk = 0 preload
                const uint32_t aoff = (uint32_t)(((0 + asel) ^ aXor) << 4);
                const uint32_t boff = (uint32_t)(((0 + bsel) ^ bXor) << 4);
                #pragma unroll
                for (int i = 0; i < 4; ++i)    ldsm_x4(fa[0][i],  sA + aBase[i]  + aoff);
                #pragma unroll
                for (int jp = 0; jp < 4; ++jp) ldsm_x4(fb[0][jp], sB + bBase[jp] + boff);
            }

            #pragma unroll
            for (int kk = 0; kk < 4; ++kk) {
                const int cur = kk & 1, nxt = cur ^ 1;
                if (kk < 3) {
                    const uint32_t aoff = (uint32_t)((((kk + 1) * 2 + asel) ^ aXor) << 4);
                    const uint32_t boff = (uint32_t)((((kk + 1) * 2 + bsel) ^ bXor) << 4);
                    #pragma unroll
                    for (int i = 0; i < 4; ++i)    ldsm_x4(fa[nxt][i],  sA + aBase[i]  + aoff);
                    #pragma unroll
                    for (int jp = 0; jp < 4; ++jp) ldsm_x4(fb[nxt][jp], sB + bBase[jp] + boff);
                }
                #pragma unroll
                for (int i = 0; i < 4; ++i)
                    #pragma unroll
                    for (int j = 0; j < 8; ++j)
                        mma_f16(acc[i][j], fa[cur][i], &fb[cur][j >> 1][(j & 1) * 2]);
            }

            // producer AFTER compute: refill stage (gi + STAGES-1), which may
            // belong to the NEXT tile — pipeline never drains at tile bounds.
            const long pf = gi + STAGES - 1;
            if (tid == 0 && pf < totIt) {
                const int s2 = (int)(pf & (STAGES - 1));
                if (pf >= STAGES)
                    MBARRIER_WAIT_PARITY(sbase + 64 + 8 * s2, (uint32_t)(((pf >> 2) - 1) & 1));
                const __half *pa, *pb;
                panels(pf, pa, pb);
                const uint32_t st = sbase + HDR + s2 * STG;
                MBARRIER_EXPECT_TX(sbase + 8 * s2, STG);
                BULK_G2S(st,        pa, A_ST, sbase + 8 * s2);
                BULK_G2S(st + A_ST, pb, B_ST, sbase + 8 * s2);
            }

            __syncwarp();
            if (lid == 0) MBARRIER_ARRIVE(sbase + 64 + 8 * s);
        }

        // ---- epilogue (overlaps with bulk loads for the next tile) ---------
        const bool has2 = (bias2 != nullptr);
        const int jb0 = n0 + warpN * 64;

        #pragma unroll
        for (int j = 0; j < 8; ++j) {
            const int col = jb0 + j * 8 + 2 * tg;
            float bb0 = bias1[col], bb1 = bias1[col + 1];
            if (has2) { bb0 += bias2[col]; bb1 += bias2[col + 1]; }
            #pragma unroll
            for (int i = 0; i < 4; ++i) {
                const long r0 = m0 + warpM * 64 + i * 16 + g;
                #pragma unroll
                for (int h = 0; h < 2; ++h) {
                    const long r = r0 + 8 * h;
                    float v0 = acc[i][j][2 * h + 0] + bb0;
                    float v1 = acc[i][j][2 * h + 1] + bb1;
                    if (RELU) { v0 = fmaxf(v0, 0.0f); v1 = fmaxf(v1, 0.0f); }
                    if (HALF_OUT) {
                        // swizzled 128-row panel layout (next GEMM's A operand)
                        __half2 hv = __floats2half2_rn(v0, v1);
                        const size_t panel = ((size_t)(r >> 7) * (N >> 6) + (col >> 6)) << 13;
                        const size_t off = panel + (size_t)((int)(r & 127)) * 64
                                         + (size_t)(((((col >> 3) & 7) ^ ((int)r & 7)) << 3) + (col & 7));
                        *reinterpret_cast<uint32_t*>((__half*)Cv + off) =
                            *reinterpret_cast<uint32_t*>(&hv);
                    } else {
                        *reinterpret_cast<float2*>((float*)Cv + (size_t)r * N + col) =
                            make_float2(v0, v1);
                    }
                }
            }
        }
    }
}

// ----------------------------------------------------------------------------
// Host launcher
// ----------------------------------------------------------------------------
extern "C" void kernel_launch(void* const* d_in, const int* in_sizes, int n_in,
                              void* d_out, int out_size)
{
    const float* x    = (const float*)d_in[0];
    const float* W1   = (const float*)d_in[1];
    const float* b1   = (const float*)d_in[2];
    const float* W2   = (const float*)d_in[3];
    const float* bih  = (const float*)d_in[4];
    const float* bhh  = (const float*)d_in[5];
    const float* W3   = (const float*)d_in[6];
    const float* b3   = (const float*)d_in[7];
    float* out = (float*)d_out;

    __half *gx, *gh, *go, *gw1, *gw2, *gw3;
    cudaGetSymbolAddress((void**)&gx,  g_x);
    cudaGetSymbolAddress((void**)&gh,  g_h);
    cudaGetSymbolAddress((void**)&go,  g_o);
    cudaGetSymbolAddress((void**)&gw1, g_w1);
    cudaGetSymbolAddress((void**)&gw2, g_w2);
    cudaGetSymbolAddress((void**)&gw3, g_w3);

    cudaFuncSetAttribute(gemm_f16_kernel<true, true>,
                         cudaFuncAttributeMaxDynamicSharedMemorySize, SMEM_TOTAL);
    cudaFuncSetAttribute(gemm_f16_kernel<false, false>,
                         cudaFuncAttributeMaxDynamicSharedMemorySize, SMEM_TOTAL);

    int nsm = 148;
    cudaDeviceGetAttribute(&nsm, cudaDevAttrMultiProcessorCount, 0);

    // fused pre-pass: fp32 -> fp16 into swizzled panels (single launch)
    {
        CvtSeg s0 = { x,  gx,  (int)(MTOK * (long)DIN / 8), 7, 7 };   // RP=128
        CvtSeg s1 = { W1, gw1, (int)((long)DH * DIN / 8),   7, 8 };   // RP=256
        CvtSeg s2 = { W2, gw2, (int)((long)DH * DH / 8),    8, 8 };
        CvtSeg s3 = { W3, gw3, (int)((long)DACT * DH / 8),  8, 8 };
        const int total = s0.ng + s1.ng + s2.ng + s3.ng;
        cvt_all_kernel<<<2048, 512>>>(s0, s1, s2, s3, total);
    }

    const int Mtiles = (int)(MTOK / BM);   // 256

    // GEMM1: h = relu(x @ W1^T + b1) -> fp16 panels   (KT=16, ktlog=4, ntlog=3)
    gemm_f16_kernel<true, true><<<nsm, NTHR, SMEM_TOTAL>>>(
        gx, gw1, gh, b1, nullptr, DH, 4, 3, Mtiles * (DH / BN));

    // GEMM2: o = relu(h @ W2^T + bih + bhh) -> fp16 panels (KT=32, ktlog=5, ntlog=3)
    gemm_f16_kernel<true, true><<<nsm, NTHR, SMEM_TOTAL>>>(
        gh, gw2, go, bih, bhh, DH, 5, 3, Mtiles * (DH / BN));

    // GEMM3: y = o @ W3^T + b3 -> fp32 row-major      (KT=32, ktlog=5, ntlog=2)
    gemm_f16_kernel<false, false><<<nsm, NTHR, SMEM_TOTAL>>>(
        go, gw3, out, b3, nullptr, DACT, 5, 2, Mtiles * (DACT / BN));

    (void)in_sizes; (void)n_in; (void)out_size;
}